// round 14
// baseline (speedup 1.0000x reference)
#include <cuda_runtime.h>
#include <math.h>

// Shapes (fixed by the problem)
#define BB 64      // batch
#define DD 512     // in dims
#define PP 128     // patches
#define NM 1152    // P*9 mask logits per batch
#define NT 768     // P*6 theta per batch
#define NO 1920    // NM + NT
#define SS 64      // scene size

// GEMM tiling (R12 config)
#define KSPLIT 16
#define KCH 32
#define OT 64
#define PAD 4

__device__ float g_part[KSPLIT][BB * NO];   // k-split partials (L2-resident)
__device__ float g_masks[BB * NM];          // (1-sigmoid)*noise
__device__ float g_theta[BB * NT];          // theta + bias

// ---------------------------------------------------------------------------
// Kernel A: partial GEMM (R12 version, fp32 weights).
// ---------------------------------------------------------------------------
__global__ __launch_bounds__(256) void gemm_part_kernel(
    const float* __restrict__ z, const float* __restrict__ Wm,
    const float* __restrict__ Wt)
{
    __shared__ float zs[BB][KCH + PAD];
    __shared__ float ws[OT][KCH + PAD];

    const int obase = blockIdx.x * OT;
    const int kbase = blockIdx.y * KCH;
    const int tid = threadIdx.x;

    for (int i = tid; i < BB * (KCH / 4); i += 256) {
        int b = i >> 3, k4 = i & 7;
        float4 v = *reinterpret_cast<const float4*>(z + b * DD + kbase + 4 * k4);
        *reinterpret_cast<float4*>(&zs[b][4 * k4]) = v;
    }
    for (int i = tid; i < OT * (KCH / 4); i += 256) {
        int o = i >> 3, k4 = i & 7;
        int og = obase + o;
        const float* row = (og < NM) ? (Wm + (size_t)og * DD)
                                     : (Wt + (size_t)(og - NM) * DD);
        float4 v = *reinterpret_cast<const float4*>(row + kbase + 4 * k4);
        *reinterpret_cast<float4*>(&ws[o][4 * k4]) = v;
    }
    __syncthreads();

    const int tx = tid & 15;
    const int ty = tid >> 4;

    float acc[4][4];
#pragma unroll
    for (int i = 0; i < 4; i++)
#pragma unroll
        for (int j = 0; j < 4; j++) acc[i][j] = 0.f;

#pragma unroll
    for (int k0 = 0; k0 < KCH; k0 += 4) {
        float4 wv[4], zv[4];
#pragma unroll
        for (int i = 0; i < 4; i++)
            wv[i] = *reinterpret_cast<const float4*>(&ws[tx + 16 * i][k0]);
#pragma unroll
        for (int j = 0; j < 4; j++)
            zv[j] = *reinterpret_cast<const float4*>(&zs[ty + 16 * j][k0]);
#pragma unroll
        for (int i = 0; i < 4; i++)
#pragma unroll
            for (int j = 0; j < 4; j++) {
                acc[i][j] = fmaf(wv[i].x, zv[j].x, acc[i][j]);
                acc[i][j] = fmaf(wv[i].y, zv[j].y, acc[i][j]);
                acc[i][j] = fmaf(wv[i].z, zv[j].z, acc[i][j]);
                acc[i][j] = fmaf(wv[i].w, zv[j].w, acc[i][j]);
            }
    }

    float* part = g_part[blockIdx.y];
#pragma unroll
    for (int j = 0; j < 4; j++) {
        int b = ty + 16 * j;
#pragma unroll
        for (int i = 0; i < 4; i++)
            part[b * NO + obase + tx + 16 * i] = acc[i][j];
    }
}

// ---------------------------------------------------------------------------
// Kernel B: reduce k-splits + nonlinearity, float4-vectorized (R13 version).
// ---------------------------------------------------------------------------
__global__ __launch_bounds__(256) void prep_kernel(
    const float* __restrict__ bm, const float* __restrict__ bt,
    const float* __restrict__ noise)
{
    const int idx = blockIdx.x * 256 + threadIdx.x;   // [0, BB*NO/4)
    const int b = idx / (NO / 4);
    const int o0 = (idx - b * (NO / 4)) * 4;
    const float4* gp = reinterpret_cast<const float4*>(&g_part[0][b * NO + o0]);
    float4 s = make_float4(0.f, 0.f, 0.f, 0.f);
#pragma unroll
    for (int kk = 0; kk < KSPLIT; kk++) {
        float4 v = gp[kk * (BB * NO / 4)];
        s.x += v.x; s.y += v.y; s.z += v.z; s.w += v.w;
    }
    const float* sp = &s.x;
#pragma unroll
    for (int c = 0; c < 4; c++) {
        const int o = o0 + c;
        if (o < NM) {
            g_masks[b * NM + o] = noise[o % 9] / (1.f + expf(sp[c] + bm[o]));
        } else {
            const int t = o - NM;
            g_theta[b * NT + t] = sp[c] + bt[t];
        }
    }
}

// f32x2 helpers: one SASS op each, operands pre-packed in 64-bit vars.
__device__ __forceinline__ unsigned long long f2_add(unsigned long long a,
                                                     unsigned long long b)
{
    unsigned long long r;
    asm("add.rn.f32x2 %0, %1, %2;" : "=l"(r) : "l"(a), "l"(b));
    return r;
}
__device__ __forceinline__ unsigned long long f2_add_rz(unsigned long long a,
                                                        unsigned long long b)
{
    unsigned long long r;
    asm("add.rz.f32x2 %0, %1, %2;" : "=l"(r) : "l"(a), "l"(b));
    return r;
}
__device__ __forceinline__ unsigned long long f2_fma(unsigned long long a,
                                                     unsigned long long b,
                                                     unsigned long long c)
{
    unsigned long long r;
    asm("fma.rn.f32x2 %0, %1, %2, %3;" : "=l"(r) : "l"(a), "l"(b), "l"(c));
    return r;
}
__device__ __forceinline__ unsigned long long f2_pack(float x, float y)
{
    unsigned long long r;
    asm("mov.b64 %0, {%1, %2};" : "=l"(r) : "f"(x), "f"(y));
    return r;
}

// ---------------------------------------------------------------------------
// Kernel C: render. 18x16 zero plane -> 256-cell float4 bilinear LUT.
// Packed f32x2 coordinate math: {ix,iy} add, magic rz-floor, unbias, frac —
// 4 FP issue slots per pixel for both axes. Index/weights extracted by
// register aliasing (uint2/float2 views), no unpack movs.
// Wrapped OOR indices land only in all-zero cells (validated R10/R12).
// ---------------------------------------------------------------------------
__global__ __launch_bounds__(256) void render_kernel(float* __restrict__ out)
{
    const int bp = blockIdx.x;          // b*128 + p
    const int b = bp >> 7, p = bp & 127;

    __shared__ float  smp[288];         // 18x16 zero plane
    __shared__ float4 qtab[256];        // 16x16 bilinear cells
    __shared__ float  st[6];
    const int tid = threadIdx.x;

    for (int i = tid; i < 288; i += 256) smp[i] = 0.f;
    __syncthreads();
    if (tid < 9)
        smp[((tid / 3) + 2) * 16 + (tid % 3) + 2] = g_masks[b * NM + p * 9 + tid];
    else if (tid >= 16 && tid < 22)
        st[tid - 16] = g_theta[b * NT + p * 6 + (tid - 16)];
    __syncthreads();
    {
        const float v00 = smp[tid];
        const float v01 = smp[tid + 1];
        const float v10 = smp[tid + 16];
        const float v11 = smp[tid + 17];
        qtab[tid] = make_float4(v00, v01 - v00, v10 - v00, v11 - v10 - v01 + v00);
    }
    __syncthreads();

    const float t00 = st[0], t01 = st[1], t02 = st[2];
    const float t10 = st[3], t11 = st[4], t12 = st[5];

    // table coord = 1.5*(theta . [cx,cy,1]) + 3   (mask at [2..4])
    const int xq = (tid & 15) << 2;
    const int y0 = tid >> 4;

    unsigned long long a2[4];           // packed {ax, ay} per column d
#pragma unroll
    for (int d = 0; d < 4; d++) {
        const float cx = (xq + d + 0.5f) * (1.f / 32.f) - 1.f;
        a2[d] = f2_pack(1.5f * t00 * cx, 1.5f * t10 * cx);
    }
    const float ct01 = 1.5f * t01, ct11 = 1.5f * t11;
    const float cx0  = fmaf(1.5f, t02, 3.f);
    const float cy0  = fmaf(1.5f, t12, 3.f);

    const unsigned long long MAGIC2  = 0x4B4000004B400000ULL;  // {1.5*2^23}x2
    const unsigned long long NMAGIC2 = 0xCB400000CB400000ULL;  // negated
    const unsigned long long NEG1_2  = 0xBF800000BF800000ULL;  // {-1,-1}

    const unsigned qbase = (unsigned)__cvta_generic_to_shared(qtab);
    float4* o4 = reinterpret_cast<float4*>(out + (size_t)bp * (SS * SS));

#pragma unroll
    for (int it = 0; it < 4; it++) {
        const int y = y0 + 16 * it;
        const float cy = (y + 0.5f) * (1.f / 32.f) - 1.f;
        const unsigned long long b2 =
            f2_pack(fmaf(ct01, cy, cx0), fmaf(ct11, cy, cy0));
        float4 r;
        float* rp = &r.x;
#pragma unroll
        for (int d = 0; d < 4; d++) {
            const unsigned long long c2 = f2_add(a2[d], b2);        // {ix, iy}
            const unsigned long long t2 = f2_add_rz(c2, MAGIC2);    // biased floor
            const unsigned long long f2 = f2_add(t2, NMAGIC2);      // {fx, fy}
            const unsigned long long w2 = f2_fma(f2, NEG1_2, c2);   // {wx, wy}
            const uint2  tb = *reinterpret_cast<const uint2*>(&t2);
            const float2 wf = *reinterpret_cast<const float2*>(&w2);
            const unsigned adr = qbase + ((tb.x & 15u) << 4) + ((tb.y & 15u) << 8);
            float4 q;
            asm("ld.shared.v4.f32 {%0, %1, %2, %3}, [%4];"
                : "=f"(q.x), "=f"(q.y), "=f"(q.z), "=f"(q.w) : "r"(adr));
            const float va = fmaf(wf.x, q.y, q.x);    // v00 + wx*dx
            const float vb = fmaf(wf.x, q.w, q.z);    // dy + wx*dxy
            rp[d] = fmaf(wf.y, vb, va);
        }
        __stcs(o4 + (y << 4) + (xq >> 2), r);
    }
}

extern "C" void kernel_launch(void* const* d_in, const int* in_sizes, int n_in,
                              void* d_out, int out_size)
{
    const float* z     = (const float*)d_in[0];
    const float* Wm    = (const float*)d_in[1];
    const float* bm    = (const float*)d_in[2];
    const float* Wt    = (const float*)d_in[3];
    const float* bt    = (const float*)d_in[4];
    const float* noise = (const float*)d_in[5];
    float* out = (float*)d_out;

    gemm_part_kernel<<<dim3(NO / OT, KSPLIT), 256>>>(z, Wm, Wt);
    prep_kernel<<<BB * NO / 4 / 256, 256>>>(bm, bt, noise);
    render_kernel<<<BB * PP, 256>>>(out);
}

// round 15
// speedup vs baseline: 1.5361x; 1.5361x over previous
#include <cuda_runtime.h>
#include <cuda_fp16.h>
#include <math.h>

// Shapes (fixed by the problem)
#define BB 64      // batch
#define DD 512     // in dims
#define PP 128     // patches
#define NM 1152    // P*9 mask logits per batch
#define NT 768     // P*6 theta per batch
#define NO 1920    // NM + NT
#define SS 64      // scene size

// GEMM tiling (R12 config — best measured)
#define KSPLIT 16
#define KCH 32
#define OT 64
#define PAD 4

__device__ float g_part[KSPLIT][BB * NO];   // k-split partials (L2-resident)
__device__ float g_masks[BB * NM];          // (1-sigmoid)*noise
__device__ float g_theta[BB * NT];          // theta + bias

// ---------------------------------------------------------------------------
// Kernel A: partial GEMM (R12 version, fp32 weights).
// ---------------------------------------------------------------------------
__global__ __launch_bounds__(256) void gemm_part_kernel(
    const float* __restrict__ z, const float* __restrict__ Wm,
    const float* __restrict__ Wt)
{
    __shared__ float zs[BB][KCH + PAD];
    __shared__ float ws[OT][KCH + PAD];

    const int obase = blockIdx.x * OT;
    const int kbase = blockIdx.y * KCH;
    const int tid = threadIdx.x;

    for (int i = tid; i < BB * (KCH / 4); i += 256) {
        int b = i >> 3, k4 = i & 7;
        float4 v = *reinterpret_cast<const float4*>(z + b * DD + kbase + 4 * k4);
        *reinterpret_cast<float4*>(&zs[b][4 * k4]) = v;
    }
    for (int i = tid; i < OT * (KCH / 4); i += 256) {
        int o = i >> 3, k4 = i & 7;
        int og = obase + o;
        const float* row = (og < NM) ? (Wm + (size_t)og * DD)
                                     : (Wt + (size_t)(og - NM) * DD);
        float4 v = *reinterpret_cast<const float4*>(row + kbase + 4 * k4);
        *reinterpret_cast<float4*>(&ws[o][4 * k4]) = v;
    }
    __syncthreads();

    const int tx = tid & 15;
    const int ty = tid >> 4;

    float acc[4][4];
#pragma unroll
    for (int i = 0; i < 4; i++)
#pragma unroll
        for (int j = 0; j < 4; j++) acc[i][j] = 0.f;

#pragma unroll
    for (int k0 = 0; k0 < KCH; k0 += 4) {
        float4 wv[4], zv[4];
#pragma unroll
        for (int i = 0; i < 4; i++)
            wv[i] = *reinterpret_cast<const float4*>(&ws[tx + 16 * i][k0]);
#pragma unroll
        for (int j = 0; j < 4; j++)
            zv[j] = *reinterpret_cast<const float4*>(&zs[ty + 16 * j][k0]);
#pragma unroll
        for (int i = 0; i < 4; i++)
#pragma unroll
            for (int j = 0; j < 4; j++) {
                acc[i][j] = fmaf(wv[i].x, zv[j].x, acc[i][j]);
                acc[i][j] = fmaf(wv[i].y, zv[j].y, acc[i][j]);
                acc[i][j] = fmaf(wv[i].z, zv[j].z, acc[i][j]);
                acc[i][j] = fmaf(wv[i].w, zv[j].w, acc[i][j]);
            }
    }

    float* part = g_part[blockIdx.y];
#pragma unroll
    for (int j = 0; j < 4; j++) {
        int b = ty + 16 * j;
#pragma unroll
        for (int i = 0; i < 4; i++)
            part[b * NO + obase + tx + 16 * i] = acc[i][j];
    }
}

// ---------------------------------------------------------------------------
// Kernel B: reduce k-splits + nonlinearity, float4-vectorized (R13 version).
// ---------------------------------------------------------------------------
__global__ __launch_bounds__(256) void prep_kernel(
    const float* __restrict__ bm, const float* __restrict__ bt,
    const float* __restrict__ noise)
{
    const int idx = blockIdx.x * 256 + threadIdx.x;   // [0, BB*NO/4)
    const int b = idx / (NO / 4);
    const int o0 = (idx - b * (NO / 4)) * 4;
    const float4* gp = reinterpret_cast<const float4*>(&g_part[0][b * NO + o0]);
    float4 s = make_float4(0.f, 0.f, 0.f, 0.f);
#pragma unroll
    for (int kk = 0; kk < KSPLIT; kk++) {
        float4 v = gp[kk * (BB * NO / 4)];
        s.x += v.x; s.y += v.y; s.z += v.z; s.w += v.w;
    }
    const float* sp = &s.x;
#pragma unroll
    for (int c = 0; c < 4; c++) {
        const int o = o0 + c;
        if (o < NM) {
            g_masks[b * NM + o] = noise[o % 9] / (1.f + expf(sp[c] + bm[o]));
        } else {
            const int t = o - NM;
            g_theta[b * NT + t] = sp[c] + bt[t];
        }
    }
}

// ---------------------------------------------------------------------------
// Kernel C: render. 18x16 zero plane -> 256-cell fp16 bilinear LUT:
//   cell = { half2{v00, dy}, half2{dx, dxy} }   (8 bytes, LDS.64)
//   vab  = hfma2({wx,wx}, {dx,dxy}, {v00,dy}) -> {va, vb}
//   out  = fmaf(wy, vb, va)
// Coordinate math stays fp32 (magic-number floor, index from mantissa bits).
// Wrapped OOR indices land only in all-zero cells (validated R10/R12).
// ---------------------------------------------------------------------------
__global__ __launch_bounds__(256) void render_kernel(float* __restrict__ out)
{
    const int bp = blockIdx.x;          // b*128 + p
    const int b = bp >> 7, p = bp & 127;

    __shared__ float smp[288];          // 18x16 zero plane
    __shared__ uint2 qtab[256];         // 16x16 fp16 bilinear cells
    __shared__ float st[6];
    const int tid = threadIdx.x;

    for (int i = tid; i < 288; i += 256) smp[i] = 0.f;
    __syncthreads();
    if (tid < 9)
        smp[((tid / 3) + 2) * 16 + (tid % 3) + 2] = g_masks[b * NM + p * 9 + tid];
    else if (tid >= 16 && tid < 22)
        st[tid - 16] = g_theta[b * NT + p * 6 + (tid - 16)];
    __syncthreads();
    {
        const float v00 = smp[tid];
        const float v01 = smp[tid + 1];
        const float v10 = smp[tid + 16];
        const float v11 = smp[tid + 17];
        const float dx  = v01 - v00;
        const float dy  = v10 - v00;
        const float dxy = v11 - v10 - v01 + v00;
        __half2 A = __floats2half2_rn(v00, dy);   // {lo=v00, hi=dy}
        __half2 B = __floats2half2_rn(dx, dxy);   // {lo=dx,  hi=dxy}
        qtab[tid] = make_uint2(*reinterpret_cast<unsigned*>(&A),
                               *reinterpret_cast<unsigned*>(&B));
    }
    __syncthreads();

    const float t00 = st[0], t01 = st[1], t02 = st[2];
    const float t10 = st[3], t11 = st[4], t12 = st[5];

    // table coord = 1.5*(theta . [cx,cy,1]) + 3   (mask at [2..4])
    const int xq = (tid & 15) << 2;
    const int y0 = tid >> 4;

    float axd[4], ayd[4];
#pragma unroll
    for (int d = 0; d < 4; d++) {
        const float cx = (xq + d + 0.5f) * (1.f / 32.f) - 1.f;
        axd[d] = 1.5f * t00 * cx;
        ayd[d] = 1.5f * t10 * cx;
    }
    const float ct01 = 1.5f * t01, ct11 = 1.5f * t11;
    const float cx0  = fmaf(1.5f, t02, 3.f);
    const float cy0  = fmaf(1.5f, t12, 3.f);

    const float MAGICF = 12582912.f;    // 1.5 * 2^23
    float4* o4 = reinterpret_cast<float4*>(out + (size_t)bp * (SS * SS));

#pragma unroll
    for (int it = 0; it < 4; it++) {
        const int y = y0 + 16 * it;
        const float cy = (y + 0.5f) * (1.f / 32.f) - 1.f;
        const float bx = fmaf(ct01, cy, cx0);
        const float by = fmaf(ct11, cy, cy0);
        float4 r;
        float* rp = &r.x;
#pragma unroll
        for (int d = 0; d < 4; d++) {
            const float ix = axd[d] + bx;
            const float iy = ayd[d] + by;
            const float tx = __fadd_rz(ix, MAGICF);   // floor in mantissa
            const float ty = __fadd_rz(iy, MAGICF);
            const float fx = tx - MAGICF;             // exact floor as float
            const float fy = ty - MAGICF;
            const float wx = ix - fx;
            const float wy = iy - fy;
            const unsigned xi = __float_as_uint(tx) & 15u;
            const unsigned yi = __float_as_uint(ty) & 15u;
            const uint2 q = qtab[(yi << 4) | xi];     // LDS.64
            const __half2 A = *reinterpret_cast<const __half2*>(&q.x);
            const __half2 Bc = *reinterpret_cast<const __half2*>(&q.y);
            const __half2 wx2 = __float2half2_rn(wx);
            const __half2 vab = __hfma2(wx2, Bc, A);  // {va, vb}
            const float2 f = __half22float2(vab);
            rp[d] = fmaf(wy, f.y, f.x);
        }
        __stcs(o4 + (y << 4) + (xq >> 2), r);
    }
}

extern "C" void kernel_launch(void* const* d_in, const int* in_sizes, int n_in,
                              void* d_out, int out_size)
{
    const float* z     = (const float*)d_in[0];
    const float* Wm    = (const float*)d_in[1];
    const float* bm    = (const float*)d_in[2];
    const float* Wt    = (const float*)d_in[3];
    const float* bt    = (const float*)d_in[4];
    const float* noise = (const float*)d_in[5];
    float* out = (float*)d_out;

    gemm_part_kernel<<<dim3(NO / OT, KSPLIT), 256>>>(z, Wm, Wt);
    prep_kernel<<<BB * NO / 4 / 256, 256>>>(bm, bt, noise);
    render_kernel<<<BB * PP, 256>>>(out);
}